// round 15
// baseline (speedup 1.0000x reference)
#include <cuda_runtime.h>
#include <cuda_fp16.h>
#include <cstdint>

#define B_ 64
#define N_ 2048
#define H_ 512
#define D_ 512
#define A_ 512
#define M_ (B_*N_)
#define NEG_INF_ -1.0e9f

// prep grid split (proj_h | wconv only)
#define NB_PROJ  4096
#define NB_WCONV 1024
#define NB_PREP  (NB_PROJ + NB_WCONV)

// ---------------- persistent device scratch ----------------
__device__ float g_proj_h[B_*A_];
__device__ float g_scores[M_];
__device__ __align__(16) __half g_We_h[A_*D_];
__device__ __align__(16) __half g_enc_h[(size_t)M_*D_];   // written by scores (ci<8), read by sc

__device__ __forceinline__ uint32_t smem_u32(const void* p) {
    uint32_t a;
    asm("{ .reg .u64 t; cvta.to.shared.u64 t, %1; cvt.u32.u64 %0, t; }" : "=r"(a) : "l"(p));
    return a;
}

#define LDSM_X4(r, addr)                                                          \
    asm volatile("ldmatrix.sync.aligned.m8n8.x4.shared.b16 {%0,%1,%2,%3}, [%4];"  \
        : "=r"((r)[0]), "=r"((r)[1]), "=r"((r)[2]), "=r"((r)[3]) : "r"(addr))

#define MMA_F16(d, a, b0, b1)                                                     \
    asm volatile("mma.sync.aligned.m16n8k16.row.col.f32.f16.f16.f32 "             \
        "{%0,%1,%2,%3}, {%4,%5,%6,%7}, {%8,%9}, {%0,%1,%2,%3};"                   \
        : "+f"((d)[0]), "+f"((d)[1]), "+f"((d)[2]), "+f"((d)[3])                  \
        : "r"((a)[0]), "r"((a)[1]), "r"((a)[2]), "r"((a)[3]), "r"(b0), "r"(b1))

#define CP16(dst, src)  asm volatile("cp.async.cg.shared.global [%0], [%1], 16;" :: "r"(dst), "l"(src))
#define CP_COMMIT()     asm volatile("cp.async.commit_group;" ::: "memory")
#define CP_WAIT1()      asm volatile("cp.async.wait_group 1;" ::: "memory")
#define CP_WAIT0()      asm volatile("cp.async.wait_group 0;" ::: "memory")

// smem: 2 stages {E32 64x64 fp32 (256B rows, linear) 16KB, W 256x64 fp16 32KB}
//       + single shared fp16 E buffer 8KB + vs/ps/red
#define STGSZ   49152
#define OFF_E32 0
#define OFF_W   16384
#define OFF_EH  (2*STGSZ)              // 98304, 8KB fp16 E (single buffer)
#define OFF_VS  (OFF_EH + 8192)
#define OFF_PS  (OFF_VS + 2048)
#define OFF_RED (OFF_PS + 2048)
#define SMEM_BYTES (OFF_RED + 1024)    // 111616 B/CTA -> 2 CTAs/SM

// ---------------------------------------------------------------------------
// prep: proj_h | wconv
// ---------------------------------------------------------------------------
__global__ void prep_kernel(const float* __restrict__ h,
                            const float* __restrict__ Wh,
                            const float* __restrict__ We) {
    const int blk = blockIdx.x;
    const int tid = threadIdx.x;
    if (blk < NB_PROJ) {               // proj_h: warp per output
        int gw   = blk * 8 + (tid >> 5);
        int lane = tid & 31;
        int b = gw / A_, a = gw % A_;
        const float* hr = h  + (size_t)b * H_;
        const float* wr = Wh + (size_t)a * H_;
        float s = 0.f;
        #pragma unroll 4
        for (int k = lane; k < H_; k += 32) s += hr[k] * wr[k];
        #pragma unroll
        for (int o = 16; o > 0; o >>= 1) s += __shfl_xor_sync(0xffffffffu, s, o);
        if (lane == 0) g_proj_h[(size_t)b * A_ + a] = s;
    } else {                           // wconv
        int i = (blk - NB_PROJ) * 256 + tid;
        g_We_h[i] = __float2half_rn(We[i]);
    }
}

// ---------------------------------------------------------------------------
// scores: fp16 HMMA; enc arrives as fp32 via cp.async, converted smem->smem.
// 256-thread CTA, M-tile 64, 2 CTAs/SM.
// Per iter: issue(ci+1) -> WAIT1 -> syncA -> convert E(ci) fp32->fp16 (+STG
// first sweep) -> syncB -> compute(ci) -> syncC.
// 16 iters = 2 a-chunks x 8 K-chunks of 64. Fused tanh.approx/v epilogue.
// ---------------------------------------------------------------------------
__global__ __launch_bounds__(256, 2)
void scores_kernel(const float* __restrict__ enc, const float* __restrict__ v) {
    extern __shared__ char smem[];
    const uint32_t sb = smem_u32(smem);
    const int tid  = threadIdx.x;
    const int lane = tid & 31;
    const int w    = tid >> 5;
    const int wm   = w & 1;
    const int wn   = w >> 1;
    const int m0   = blockIdx.x * 64;
    const int b    = blockIdx.x >> 5;

    float* vs = (float*)(smem + OFF_VS);
    float* ps = (float*)(smem + OFF_PS);
    #pragma unroll
    for (int i = 0; i < 2; i++) {
        vs[tid + i * 256] = v[tid + i * 256];
        ps[tid + i * 256] = g_proj_h[(size_t)b * A_ + tid + i * 256];
    }

    // E fp32 cp.async coords: 4 segs/thread (1024 total)
    uint32_t e32Dst[4]; const float* e32Src[4];
    #pragma unroll
    for (int i = 0; i < 4; i++) {
        int idx = tid + i * 256, row = idx >> 4, seg = idx & 15;
        e32Dst[i] = OFF_E32 + (uint32_t)row * 256 + (uint32_t)seg * 16;
        e32Src[i] = enc + (size_t)(m0 + row) * D_ + seg * 4;
    }
    // W cp.async coords: 8 segs/thread
    uint32_t wDst[8]; const __half* wSrc[8];
    #pragma unroll
    for (int i = 0; i < 8; i++) {
        int idx = tid + i * 256, row = idx >> 3, seg = idx & 7;
        wDst[i] = OFF_W + (uint32_t)row * 128 + (((uint32_t)seg * 16) ^ (((uint32_t)row & 7) * 16));
        wSrc[i] = g_We_h + (size_t)row * D_ + seg * 8;
    }
    // convert coords: 2 fp16 segs/thread
    const int crow0 = tid >> 3,       chs0 = tid & 7;
    const int crow1 = (tid + 256) >> 3, chs1 = tid & 7;
    const uint32_t cSrc0 = OFF_E32 + (uint32_t)crow0 * 256 + (uint32_t)chs0 * 32;
    const uint32_t cSrc1 = OFF_E32 + (uint32_t)crow1 * 256 + (uint32_t)chs1 * 32;
    const uint32_t cDst0 = OFF_EH + (uint32_t)crow0 * 128 + (((uint32_t)chs0 * 16) ^ (((uint32_t)crow0 & 7) * 16));
    const uint32_t cDst1 = OFF_EH + (uint32_t)crow1 * 128 + (((uint32_t)chs1 * 16) ^ (((uint32_t)crow1 & 7) * 16));
    __half* gOut0 = g_enc_h + (size_t)(m0 + crow0) * D_ + chs0 * 8;
    __half* gOut1 = g_enc_h + (size_t)(m0 + crow1) * D_ + chs1 * 8;

    // ldmatrix lane geometry (E from OFF_EH, W from stage)
    const uint32_t xr = (uint32_t)(lane & 7) * 16;
    const uint32_t eBase = OFF_EH + (uint32_t)(wm * 32 + (lane & 15)) * 128;
    const uint32_t eT = (uint32_t)(lane >> 4) * 16;
    const int q = lane >> 3;
    const uint32_t wBase = OFF_W + (uint32_t)(wn * 64 + ((q >> 1) << 3) + (lane & 7)) * 128;
    const uint32_t wT = (uint32_t)(q & 1) * 16;

    float c[2][8][4];
    float sp[4] = {0.f, 0.f, 0.f, 0.f};
    #pragma unroll
    for (int i = 0; i < 2; i++)
        #pragma unroll
        for (int j = 0; j < 8; j++)
            #pragma unroll
            for (int e = 0; e < 4; e++) c[i][j][e] = 0.f;

    auto issue = [&](int ci) {
        const int koff = (ci & 7) * 64;
        const int woff = (ci >> 3) * 256 * D_ + koff;
        const uint32_t st = sb + (uint32_t)(ci & 1) * STGSZ;
        #pragma unroll
        for (int i = 0; i < 4; i++)
            CP16(st + e32Dst[i], (const char*)(e32Src[i] + koff));
        #pragma unroll
        for (int i = 0; i < 8; i++)
            CP16(st + wDst[i], (const char*)(wSrc[i] + woff));
    };

    issue(0); CP_COMMIT();

    #pragma unroll 1
    for (int ci = 0; ci < 16; ci++) {
        if (ci + 1 < 16) { issue(ci + 1); CP_COMMIT(); CP_WAIT1(); }
        else             { CP_WAIT0(); }
        __syncthreads();   // syncA: stage ci (E32 + W) visible to all threads

        // convert E(ci): fp32 smem -> fp16 smem (+ STG copy on first sweep)
        const uint32_t stoff = (uint32_t)(ci & 1) * STGSZ;
        {
            uint4 a0 = *(const uint4*)(smem + stoff + cSrc0);
            uint4 a1 = *(const uint4*)(smem + stoff + cSrc0 + 16);
            uint4 b0 = *(const uint4*)(smem + stoff + cSrc1);
            uint4 b1 = *(const uint4*)(smem + stoff + cSrc1 + 16);
            uint4 ra, rb;
            asm("cvt.rn.f16x2.f32 %0, %1, %2;" : "=r"(ra.x) : "r"(a0.y), "r"(a0.x));
            asm("cvt.rn.f16x2.f32 %0, %1, %2;" : "=r"(ra.y) : "r"(a0.w), "r"(a0.z));
            asm("cvt.rn.f16x2.f32 %0, %1, %2;" : "=r"(ra.z) : "r"(a1.y), "r"(a1.x));
            asm("cvt.rn.f16x2.f32 %0, %1, %2;" : "=r"(ra.w) : "r"(a1.w), "r"(a1.z));
            asm("cvt.rn.f16x2.f32 %0, %1, %2;" : "=r"(rb.x) : "r"(b0.y), "r"(b0.x));
            asm("cvt.rn.f16x2.f32 %0, %1, %2;" : "=r"(rb.y) : "r"(b0.w), "r"(b0.z));
            asm("cvt.rn.f16x2.f32 %0, %1, %2;" : "=r"(rb.z) : "r"(b1.y), "r"(b1.x));
            asm("cvt.rn.f16x2.f32 %0, %1, %2;" : "=r"(rb.w) : "r"(b1.w), "r"(b1.z));
            *(uint4*)(smem + cDst0) = ra;
            *(uint4*)(smem + cDst1) = rb;
            if (ci < 8) {
                const int koff = ci * 64;
                *(uint4*)(gOut0 + koff) = ra;
                *(uint4*)(gOut1 + koff) = rb;
            }
        }
        __syncthreads();   // syncB: fp16 E complete

        #pragma unroll
        for (int s = 0; s < 4; s++) {
            uint32_t aF[2][4];
            #pragma unroll
            for (int i = 0; i < 2; i++)
                LDSM_X4(aF[i], sb + eBase + (uint32_t)i * 2048 + (((uint32_t)s * 32 + eT) ^ xr));
            #pragma unroll
            for (int g = 0; g < 4; g++) {
                uint32_t bF[4];
                LDSM_X4(bF, sb + stoff + wBase + (uint32_t)g * 2048 + (((uint32_t)s * 32 + wT) ^ xr));
                #pragma unroll
                for (int i = 0; i < 2; i++) {
                    MMA_F16(c[i][2*g],   aF[i], bF[0], bF[1]);
                    MMA_F16(c[i][2*g+1], aF[i], bF[2], bF[3]);
                }
            }
        }

        if ((ci & 7) == 7) {
            const int a0c = (ci >> 3) * 256;
            #pragma unroll
            for (int i = 0; i < 2; i++)
                #pragma unroll
                for (int j = 0; j < 8; j++)
                    #pragma unroll
                    for (int e = 0; e < 4; e++) {
                        int col = a0c + wn * 64 + j * 8 + (lane & 3) * 2 + (e & 1);
                        float x  = ps[col] + c[i][j][e];
                        float th;
                        asm("tanh.approx.f32 %0, %1;" : "=f"(th) : "f"(x));
                        sp[i * 2 + (e >> 1)] += vs[col] * th;
                        c[i][j][e] = 0.f;
                    }
        }
        __syncthreads();   // syncC: compute done; stage + EH free for reuse
    }

    #pragma unroll
    for (int slot = 0; slot < 4; slot++) {
        sp[slot] += __shfl_xor_sync(0xffffffffu, sp[slot], 1);
        sp[slot] += __shfl_xor_sync(0xffffffffu, sp[slot], 2);
    }
    float* red = (float*)(smem + OFF_RED);
    if ((lane & 3) == 0) {
        #pragma unroll
        for (int slot = 0; slot < 4; slot++) {
            int row = wm * 32 + (slot >> 1) * 16 + (slot & 1) * 8 + (lane >> 2);
            red[row * 4 + wn] = sp[slot];
        }
    }
    __syncthreads();
    if (tid < 64)
        g_scores[m0 + tid] = red[tid*4+0] + red[tid*4+1] + red[tid*4+2] + red[tid*4+3];
}

// ---------------------------------------------------------------------------
// fused softmax+context: grid (B, 8), 64 d-cols per block, 512 threads.
// ---------------------------------------------------------------------------
__global__ __launch_bounds__(512)
void sc_kernel(const int* __restrict__ mask,
               float* __restrict__ alpha,
               float* __restrict__ ctx) {
    __shared__ float sal[N_];
    __shared__ float sred[512];
    __shared__ float part[512 * 8];
    const int b  = blockIdx.x;
    const int d0 = blockIdx.y * 64;
    const int t  = threadIdx.x;
    const float* sc = g_scores + (size_t)b * N_;
    const int*   mk = mask     + (size_t)b * N_;

    float vals[4];
    float mx = -3.4e38f;
    #pragma unroll
    for (int i = 0; i < 4; i++) {
        int n = t + i * 512;
        float s = (mk[n] == 0) ? NEG_INF_ : sc[n];
        vals[i] = s;
        mx = fmaxf(mx, s);
    }
    sred[t] = mx;
    __syncthreads();
    #pragma unroll
    for (int o = 256; o > 0; o >>= 1) {
        if (t < o) sred[t] = fmaxf(sred[t], sred[t + o]);
        __syncthreads();
    }
    mx = sred[0];
    __syncthreads();
    float sum = 0.f;
    #pragma unroll
    for (int i = 0; i < 4; i++) { vals[i] = expf(vals[i] - mx); sum += vals[i]; }
    sred[t] = sum;
    __syncthreads();
    #pragma unroll
    for (int o = 256; o > 0; o >>= 1) {
        if (t < o) sred[t] += sred[t + o];
        __syncthreads();
    }
    const float inv = 1.f / sred[0];
    #pragma unroll
    for (int i = 0; i < 4; i++) {
        int n = t + i * 512;
        float a = vals[i] * inv;
        sal[n] = a;
        if (blockIdx.y == 0) alpha[(size_t)b * N_ + n] = a;
    }
    __syncthreads();

    const int dg = t & 7;
    const int nl = t >> 3;
    const __half* base = g_enc_h + (size_t)b * N_ * D_ + d0 + dg * 8;

    float acc[8];
    #pragma unroll
    for (int j = 0; j < 8; j++) acc[j] = 0.f;

    #pragma unroll 1
    for (int n = nl; n < N_; n += 512) {
        uint4 pk[8];
        float av[8];
        #pragma unroll
        for (int s = 0; s < 8; s++) {
            int nn = n + s * 64;
            av[s] = sal[nn];
            pk[s] = *(const uint4*)(base + (size_t)nn * D_);
        }
        #pragma unroll
        for (int s = 0; s < 8; s++) {
            float a = av[s];
            float2 f0 = __half22float2(*(const __half2*)&pk[s].x);
            float2 f1 = __half22float2(*(const __half2*)&pk[s].y);
            float2 f2 = __half22float2(*(const __half2*)&pk[s].z);
            float2 f3 = __half22float2(*(const __half2*)&pk[s].w);
            acc[0] += a * f0.x; acc[1] += a * f0.y;
            acc[2] += a * f1.x; acc[3] += a * f1.y;
            acc[4] += a * f2.x; acc[5] += a * f2.y;
            acc[6] += a * f3.x; acc[7] += a * f3.y;
        }
    }
    #pragma unroll
    for (int j = 0; j < 8; j++) part[t * 8 + j] = acc[j];
    __syncthreads();
    if (t < 64) {
        int g = t >> 3, j = t & 7;
        float s = 0.f;
        #pragma unroll
        for (int m = 0; m < 64; m++) s += part[(g + 8 * m) * 8 + j];
        ctx[(size_t)b * D_ + d0 + g * 8 + j] = s;
    }
}

// ---------------------------------------------------------------------------
extern "C" void kernel_launch(void* const* d_in, const int* in_sizes, int n_in,
                              void* d_out, int out_size) {
    const float* h    = (const float*)d_in[0];
    const float* enc  = (const float*)d_in[1];
    const int*   mask = (const int*)  d_in[2];
    const float* Wh   = (const float*)d_in[3];
    const float* We   = (const float*)d_in[4];
    const float* v    = (const float*)d_in[5];

    float* out   = (float*)d_out;
    float* ctx   = out;               // (B, D) first
    float* alpha = out + B_ * D_;     // (B, N) second

    cudaFuncSetAttribute(scores_kernel, cudaFuncAttributeMaxDynamicSharedMemorySize, SMEM_BYTES);

    prep_kernel   <<<NB_PREP, 256>>>(h, Wh, We);
    scores_kernel <<<M_ / 64, 256, SMEM_BYTES>>>(enc, v);
    sc_kernel     <<<dim3(B_, 8), 512>>>(mask, alpha, ctx);
}

// round 16
// speedup vs baseline: 1.0403x; 1.0403x over previous
#include <cuda_runtime.h>
#include <cuda_fp16.h>
#include <cstdint>

#define B_ 64
#define N_ 2048
#define H_ 512
#define D_ 512
#define A_ 512
#define M_ (B_*N_)
#define NEG_INF_ -1.0e9f

// prep grid split (econv: 4 strided streams x 8 consecutive floats per thread)
#define NB_ECONV 8192                  // 67.1M floats / 32 per-thread / 256
#define NB_PROJ  4096
#define NB_WCONV 1024
#define NB_PREP  (NB_ECONV + NB_PROJ + NB_WCONV)
#define ECONV_STRIDE8 ((size_t)NB_ECONV * 256)      // 8-float units per sweep

// ---------------- persistent device scratch ----------------
__device__ float g_proj_h[B_*A_];
__device__ float g_scores[M_];
__device__ __align__(16) __half g_We_h[A_*D_];
__device__ __align__(16) __half g_enc_h[(size_t)M_*D_];   // 128 MB

__device__ __forceinline__ uint32_t smem_u32(const void* p) {
    uint32_t a;
    asm("{ .reg .u64 t; cvta.to.shared.u64 t, %1; cvt.u32.u64 %0, t; }" : "=r"(a) : "l"(p));
    return a;
}

#define LDSM_X4(r, addr)                                                          \
    asm volatile("ldmatrix.sync.aligned.m8n8.x4.shared.b16 {%0,%1,%2,%3}, [%4];"  \
        : "=r"((r)[0]), "=r"((r)[1]), "=r"((r)[2]), "=r"((r)[3]) : "r"(addr))

#define MMA_F16(d, a, b0, b1)                                                     \
    asm volatile("mma.sync.aligned.m16n8k16.row.col.f32.f16.f16.f32 "             \
        "{%0,%1,%2,%3}, {%4,%5,%6,%7}, {%8,%9}, {%0,%1,%2,%3};"                   \
        : "+f"((d)[0]), "+f"((d)[1]), "+f"((d)[2]), "+f"((d)[3])                  \
        : "r"((a)[0]), "r"((a)[1]), "r"((a)[2]), "r"((a)[3]), "r"(b0), "r"(b1))

#define CP16(dst, src)  asm volatile("cp.async.cg.shared.global [%0], [%1], 16;" :: "r"(dst), "l"(src))
#define CP_COMMIT()     asm volatile("cp.async.commit_group;" ::: "memory")
#define CP_WAIT1()      asm volatile("cp.async.wait_group 1;" ::: "memory")
#define CP_WAIT0()      asm volatile("cp.async.wait_group 0;" ::: "memory")

// smem: 2 stages {E 64x64 fp16 (128B rows, SW128 xor), W 256x64 fp16}
#define STG     40960
#define OFF_E   0
#define OFF_W   8192
#define OFF_VS  (2*STG)
#define OFF_PS  (OFF_VS + 2048)
#define OFF_RED (OFF_PS + 2048)
#define SMEM_BYTES (OFF_RED + 1024)

// ---------------------------------------------------------------------------
// prep: fused econv | proj_h | wconv, 256-thread blocks
// ---------------------------------------------------------------------------
__global__ void prep_kernel(const float* __restrict__ enc,
                            const float* __restrict__ h,
                            const float* __restrict__ Wh,
                            const float* __restrict__ We) {
    const int blk = blockIdx.x;
    const int tid = threadIdx.x;
    if (blk < NB_ECONV) {
        // econv: 4 strided streams, each 8 consecutive floats -> one 16B store
        const size_t t0 = (size_t)blk * 256 + tid;
        float4 lo[4], hi[4];
        #pragma unroll
        for (int s = 0; s < 4; s++) {
            const float* p = enc + (t0 + (size_t)s * ECONV_STRIDE8) * 8;
            lo[s] = *(const float4*)(p);
            hi[s] = *(const float4*)(p + 4);
        }
        #pragma unroll
        for (int s = 0; s < 4; s++) {
            uint4 r;
            asm("cvt.rn.f16x2.f32 %0, %1, %2;" : "=r"(r.x) : "f"(lo[s].y), "f"(lo[s].x));
            asm("cvt.rn.f16x2.f32 %0, %1, %2;" : "=r"(r.y) : "f"(lo[s].w), "f"(lo[s].z));
            asm("cvt.rn.f16x2.f32 %0, %1, %2;" : "=r"(r.z) : "f"(hi[s].y), "f"(hi[s].x));
            asm("cvt.rn.f16x2.f32 %0, %1, %2;" : "=r"(r.w) : "f"(hi[s].w), "f"(hi[s].z));
            *(uint4*)(g_enc_h + (t0 + (size_t)s * ECONV_STRIDE8) * 8) = r;
        }
    } else if (blk < NB_ECONV + NB_PROJ) {   // proj_h: warp per output
        int gw   = (blk - NB_ECONV) * 8 + (tid >> 5);
        int lane = tid & 31;
        int b = gw / A_, a = gw % A_;
        const float* hr = h  + (size_t)b * H_;
        const float* wr = Wh + (size_t)a * H_;
        float s = 0.f;
        #pragma unroll 4
        for (int k = lane; k < H_; k += 32) s += hr[k] * wr[k];
        #pragma unroll
        for (int o = 16; o > 0; o >>= 1) s += __shfl_xor_sync(0xffffffffu, s, o);
        if (lane == 0) g_proj_h[(size_t)b * A_ + a] = s;
    } else {                           // wconv
        int i = (blk - NB_ECONV - NB_PROJ) * 256 + tid;
        g_We_h[i] = __float2half_rn(We[i]);
    }
}

// ---------------------------------------------------------------------------
// scores: single-pass fp16 HMMA. 256-thread CTA, M-tile 64, 2 CTAs/SM.
// Proven R8/R14 pipeline (issue -> commit -> WAIT1 -> sync -> compute -> sync).
// 16 iters = 2 a-chunks x 8 K-chunks of 64. Fused tanh.approx/v epilogue.
// ---------------------------------------------------------------------------
__global__ __launch_bounds__(256, 2)
void scores_kernel(const float* __restrict__ v) {
    extern __shared__ char smem[];
    const uint32_t sb = smem_u32(smem);
    const int tid  = threadIdx.x;
    const int lane = tid & 31;
    const int w    = tid >> 5;
    const int wm   = w & 1;
    const int wn   = w >> 1;
    const int m0   = blockIdx.x * 64;
    const int b    = blockIdx.x >> 5;

    float* vs = (float*)(smem + OFF_VS);
    float* ps = (float*)(smem + OFF_PS);
    #pragma unroll
    for (int i = 0; i < 2; i++) {
        vs[tid + i * 256] = v[tid + i * 256];
        ps[tid + i * 256] = g_proj_h[(size_t)b * A_ + tid + i * 256];
    }

    uint32_t eDst[2]; const __half* eSrc[2];
    #pragma unroll
    for (int i = 0; i < 2; i++) {
        int idx = tid + i * 256, row = idx >> 3, seg = idx & 7;
        eDst[i] = OFF_E + (uint32_t)row * 128 + (((uint32_t)seg * 16) ^ (((uint32_t)row & 7) * 16));
        eSrc[i] = g_enc_h + (size_t)(m0 + row) * D_ + seg * 8;
    }
    uint32_t wDst[8]; const __half* wSrc[8];
    #pragma unroll
    for (int i = 0; i < 8; i++) {
        int idx = tid + i * 256, row = idx >> 3, seg = idx & 7;
        wDst[i] = OFF_W + (uint32_t)row * 128 + (((uint32_t)seg * 16) ^ (((uint32_t)row & 7) * 16));
        wSrc[i] = g_We_h + (size_t)row * D_ + seg * 8;
    }

    const uint32_t xr = (uint32_t)(lane & 7) * 16;
    const uint32_t eBase = OFF_E + (uint32_t)(wm * 32 + (lane & 15)) * 128;
    const uint32_t eT = (uint32_t)(lane >> 4) * 16;
    const int q = lane >> 3;
    const uint32_t wBase = OFF_W + (uint32_t)(wn * 64 + ((q >> 1) << 3) + (lane & 7)) * 128;
    const uint32_t wT = (uint32_t)(q & 1) * 16;

    float c[2][8][4];
    float sp[4] = {0.f, 0.f, 0.f, 0.f};
    #pragma unroll
    for (int i = 0; i < 2; i++)
        #pragma unroll
        for (int j = 0; j < 8; j++)
            #pragma unroll
            for (int e = 0; e < 4; e++) c[i][j][e] = 0.f;

    auto issue = [&](int ci) {
        const int koff = (ci & 7) * 64;
        const int woff = (ci >> 3) * 256 * D_ + koff;
        const uint32_t st = sb + (uint32_t)(ci & 1) * STG;
        #pragma unroll
        for (int i = 0; i < 2; i++)
            CP16(st + eDst[i], (const char*)(eSrc[i] + koff));
        #pragma unroll
        for (int i = 0; i < 8; i++)
            CP16(st + wDst[i], (const char*)(wSrc[i] + woff));
    };

    issue(0); CP_COMMIT();

    #pragma unroll 1
    for (int ci = 0; ci < 16; ci++) {
        if (ci + 1 < 16) { issue(ci + 1); CP_COMMIT(); CP_WAIT1(); }
        else             { CP_WAIT0(); }
        __syncthreads();

        const uint32_t stb = sb + (uint32_t)(ci & 1) * STG;
        #pragma unroll
        for (int s = 0; s < 4; s++) {
            uint32_t aF[2][4];
            #pragma unroll
            for (int i = 0; i < 2; i++)
                LDSM_X4(aF[i], stb + eBase + (uint32_t)i * 2048 + (((uint32_t)s * 32 + eT) ^ xr));
            #pragma unroll
            for (int g = 0; g < 4; g++) {
                uint32_t bF[4];
                LDSM_X4(bF, stb + wBase + (uint32_t)g * 2048 + (((uint32_t)s * 32 + wT) ^ xr));
                #pragma unroll
                for (int i = 0; i < 2; i++) {
                    MMA_F16(c[i][2*g],   aF[i], bF[0], bF[1]);
                    MMA_F16(c[i][2*g+1], aF[i], bF[2], bF[3]);
                }
            }
        }
        __syncthreads();

        if ((ci & 7) == 7) {
            const int a0 = (ci >> 3) * 256;
            #pragma unroll
            for (int i = 0; i < 2; i++)
                #pragma unroll
                for (int j = 0; j < 8; j++)
                    #pragma unroll
                    for (int e = 0; e < 4; e++) {
                        int col = a0 + wn * 64 + j * 8 + (lane & 3) * 2 + (e & 1);
                        float x  = ps[col] + c[i][j][e];
                        float th;
                        asm("tanh.approx.f32 %0, %1;" : "=f"(th) : "f"(x));
                        sp[i * 2 + (e >> 1)] += vs[col] * th;
                        c[i][j][e] = 0.f;
                    }
        }
    }

    #pragma unroll
    for (int slot = 0; slot < 4; slot++) {
        sp[slot] += __shfl_xor_sync(0xffffffffu, sp[slot], 1);
        sp[slot] += __shfl_xor_sync(0xffffffffu, sp[slot], 2);
    }
    float* red = (float*)(smem + OFF_RED);
    __syncthreads();
    if ((lane & 3) == 0) {
        #pragma unroll
        for (int slot = 0; slot < 4; slot++) {
            int row = wm * 32 + (slot >> 1) * 16 + (slot & 1) * 8 + (lane >> 2);
            red[row * 4 + wn] = sp[slot];
        }
    }
    __syncthreads();
    if (tid < 64)
        g_scores[m0 + tid] = red[tid*4+0] + red[tid*4+1] + red[tid*4+2] + red[tid*4+3];
}

// ---------------------------------------------------------------------------
// fused softmax+context: grid (B, 8), 64 d-cols per block, 512 threads.
// context loop: 8 independent streams (MLP 8).
// ---------------------------------------------------------------------------
__global__ __launch_bounds__(512)
void sc_kernel(const int* __restrict__ mask,
               float* __restrict__ alpha,
               float* __restrict__ ctx) {
    __shared__ float sal[N_];
    __shared__ float sred[512];
    __shared__ float part[512 * 8];
    const int b  = blockIdx.x;
    const int d0 = blockIdx.y * 64;
    const int t  = threadIdx.x;
    const float* sc = g_scores + (size_t)b * N_;
    const int*   mk = mask     + (size_t)b * N_;

    float vals[4];
    float mx = -3.4e38f;
    #pragma unroll
    for (int i = 0; i < 4; i++) {
        int n = t + i * 512;
        float s = (mk[n] == 0) ? NEG_INF_ : sc[n];
        vals[i] = s;
        mx = fmaxf(mx, s);
    }
    sred[t] = mx;
    __syncthreads();
    #pragma unroll
    for (int o = 256; o > 0; o >>= 1) {
        if (t < o) sred[t] = fmaxf(sred[t], sred[t + o]);
        __syncthreads();
    }
    mx = sred[0];
    __syncthreads();
    float sum = 0.f;
    #pragma unroll
    for (int i = 0; i < 4; i++) { vals[i] = expf(vals[i] - mx); sum += vals[i]; }
    sred[t] = sum;
    __syncthreads();
    #pragma unroll
    for (int o = 256; o > 0; o >>= 1) {
        if (t < o) sred[t] += sred[t + o];
        __syncthreads();
    }
    const float inv = 1.f / sred[0];
    #pragma unroll
    for (int i = 0; i < 4; i++) {
        int n = t + i * 512;
        float a = vals[i] * inv;
        sal[n] = a;
        if (blockIdx.y == 0) alpha[(size_t)b * N_ + n] = a;
    }
    __syncthreads();

    const int dg = t & 7;
    const int nl = t >> 3;
    const __half* base = g_enc_h + (size_t)b * N_ * D_ + d0 + dg * 8;

    float acc[8];
    #pragma unroll
    for (int j = 0; j < 8; j++) acc[j] = 0.f;

    #pragma unroll 1
    for (int n = nl; n < N_; n += 512) {
        uint4 pk[8];
        float av[8];
        #pragma unroll
        for (int s = 0; s < 8; s++) {
            int nn = n + s * 64;
            av[s] = sal[nn];
            pk[s] = *(const uint4*)(base + (size_t)nn * D_);
        }
        #pragma unroll
        for (int s = 0; s < 8; s++) {
            float a = av[s];
            float2 f0 = __half22float2(*(const __half2*)&pk[s].x);
            float2 f1 = __half22float2(*(const __half2*)&pk[s].y);
            float2 f2 = __half22float2(*(const __half2*)&pk[s].z);
            float2 f3 = __half22float2(*(const __half2*)&pk[s].w);
            acc[0] += a * f0.x; acc[1] += a * f0.y;
            acc[2] += a * f1.x; acc[3] += a * f1.y;
            acc[4] += a * f2.x; acc[5] += a * f2.y;
            acc[6] += a * f3.x; acc[7] += a * f3.y;
        }
    }
    #pragma unroll
    for (int j = 0; j < 8; j++) part[t * 8 + j] = acc[j];
    __syncthreads();
    if (t < 64) {
        int g = t >> 3, j = t & 7;
        float s = 0.f;
        #pragma unroll
        for (int m = 0; m < 64; m++) s += part[(g + 8 * m) * 8 + j];
        ctx[(size_t)b * D_ + d0 + g * 8 + j] = s;
    }
}

// ---------------------------------------------------------------------------
extern "C" void kernel_launch(void* const* d_in, const int* in_sizes, int n_in,
                              void* d_out, int out_size) {
    const float* h    = (const float*)d_in[0];
    const float* enc  = (const float*)d_in[1];
    const int*   mask = (const int*)  d_in[2];
    const float* Wh   = (const float*)d_in[3];
    const float* We   = (const float*)d_in[4];
    const float* v    = (const float*)d_in[5];

    float* out   = (float*)d_out;
    float* ctx   = out;               // (B, D) first
    float* alpha = out + B_ * D_;     // (B, N) second

    cudaFuncSetAttribute(scores_kernel, cudaFuncAttributeMaxDynamicSharedMemorySize, SMEM_BYTES);

    prep_kernel   <<<NB_PREP, 256>>>(enc, h, Wh, We);
    scores_kernel <<<M_ / 64, 256, SMEM_BYTES>>>(v);
    sc_kernel     <<<dim3(B_, 8), 512>>>(mask, alpha, ctx);
}

// round 17
// speedup vs baseline: 1.0573x; 1.0164x over previous
#include <cuda_runtime.h>
#include <cuda_fp16.h>
#include <cstdint>

#define B_ 64
#define N_ 2048
#define H_ 512
#define D_ 512
#define A_ 512
#define M_ (B_*N_)
#define NEG_INF_ -1.0e9f

// prep grid split (proj_h | wconv only; econv is a scores prologue now)
#define NB_PROJ  4096
#define NB_WCONV 1024
#define NB_PREP  (NB_PROJ + NB_WCONV)

// ---------------- persistent device scratch ----------------
__device__ float g_proj_h[B_*A_];
__device__ float g_scores[M_];
__device__ __align__(16) __half g_We_h[A_*D_];
__device__ __align__(16) __half g_enc_h[(size_t)M_*D_];   // written by scores prologue, read by scores+sc

__device__ __forceinline__ uint32_t smem_u32(const void* p) {
    uint32_t a;
    asm("{ .reg .u64 t; cvta.to.shared.u64 t, %1; cvt.u32.u64 %0, t; }" : "=r"(a) : "l"(p));
    return a;
}

#define LDSM_X4(r, addr)                                                          \
    asm volatile("ldmatrix.sync.aligned.m8n8.x4.shared.b16 {%0,%1,%2,%3}, [%4];"  \
        : "=r"((r)[0]), "=r"((r)[1]), "=r"((r)[2]), "=r"((r)[3]) : "r"(addr))

#define MMA_F16(d, a, b0, b1)                                                     \
    asm volatile("mma.sync.aligned.m16n8k16.row.col.f32.f16.f16.f32 "             \
        "{%0,%1,%2,%3}, {%4,%5,%6,%7}, {%8,%9}, {%0,%1,%2,%3};"                   \
        : "+f"((d)[0]), "+f"((d)[1]), "+f"((d)[2]), "+f"((d)[3])                  \
        : "r"((a)[0]), "r"((a)[1]), "r"((a)[2]), "r"((a)[3]), "r"(b0), "r"(b1))

#define CP16(dst, src)  asm volatile("cp.async.cg.shared.global [%0], [%1], 16;" :: "r"(dst), "l"(src))
#define CP_COMMIT()     asm volatile("cp.async.commit_group;" ::: "memory")
#define CP_WAIT1()      asm volatile("cp.async.wait_group 1;" ::: "memory")
#define CP_WAIT0()      asm volatile("cp.async.wait_group 0;" ::: "memory")

// smem: 2 stages {E 64x64 fp16 (128B rows, SW128 xor), W 256x64 fp16}
#define STG     40960
#define OFF_E   0
#define OFF_W   8192
#define OFF_VS  (2*STG)
#define OFF_PS  (OFF_VS + 2048)
#define OFF_RED (OFF_PS + 2048)
#define SMEM_BYTES (OFF_RED + 1024)

// ---------------------------------------------------------------------------
// prep: proj_h | wconv, 256-thread blocks
// ---------------------------------------------------------------------------
__global__ void prep_kernel(const float* __restrict__ h,
                            const float* __restrict__ Wh,
                            const float* __restrict__ We) {
    const int blk = blockIdx.x;
    const int tid = threadIdx.x;
    if (blk < NB_PROJ) {               // proj_h: warp per output
        int gw   = blk * 8 + (tid >> 5);
        int lane = tid & 31;
        int b = gw / A_, a = gw % A_;
        const float* hr = h  + (size_t)b * H_;
        const float* wr = Wh + (size_t)a * H_;
        float s = 0.f;
        #pragma unroll 4
        for (int k = lane; k < H_; k += 32) s += hr[k] * wr[k];
        #pragma unroll
        for (int o = 16; o > 0; o >>= 1) s += __shfl_xor_sync(0xffffffffu, s, o);
        if (lane == 0) g_proj_h[(size_t)b * A_ + a] = s;
    } else {                           // wconv
        int i = (blk - NB_PROJ) * 256 + tid;
        g_We_h[i] = __float2half_rn(We[i]);
    }
}

// ---------------------------------------------------------------------------
// scores: PROLOGUE converts this CTA's 64x512 enc tile fp32->fp16 into
// g_enc_h (transient regs, no mainloop impact), then the proven R8/R14
// mainloop runs unchanged, cp.asyncing the tile back from L2.
// 256-thread CTA, M-tile 64, 2 CTAs/SM.
// ---------------------------------------------------------------------------
__global__ __launch_bounds__(256, 2)
void scores_kernel(const float* __restrict__ enc, const float* __restrict__ v) {
    extern __shared__ char smem[];
    const uint32_t sb = smem_u32(smem);
    const int tid  = threadIdx.x;
    const int lane = tid & 31;
    const int w    = tid >> 5;
    const int wm   = w & 1;
    const int wn   = w >> 1;
    const int m0   = blockIdx.x * 64;
    const int b    = blockIdx.x >> 5;

    // ---- prologue: convert own enc tile (32768 floats) ----
    {
        const float* src = enc     + (size_t)m0 * D_;
        __half*      dst = g_enc_h + (size_t)m0 * D_;
        #pragma unroll
        for (int i = 0; i < 16; i++) {
            int idx = (tid + i * 256) * 8;           // 8 consecutive floats
            float4 lo = *(const float4*)(src + idx);
            float4 hi = *(const float4*)(src + idx + 4);
            uint4 r;
            asm("cvt.rn.f16x2.f32 %0, %1, %2;" : "=r"(r.x) : "f"(lo.y), "f"(lo.x));
            asm("cvt.rn.f16x2.f32 %0, %1, %2;" : "=r"(r.y) : "f"(lo.w), "f"(lo.z));
            asm("cvt.rn.f16x2.f32 %0, %1, %2;" : "=r"(r.z) : "f"(hi.y), "f"(hi.x));
            asm("cvt.rn.f16x2.f32 %0, %1, %2;" : "=r"(r.w) : "f"(hi.w), "f"(hi.z));
            *(uint4*)(dst + idx) = r;
        }
    }
    // vs/ps loads (independent of prologue)
    float* vs = (float*)(smem + OFF_VS);
    float* ps = (float*)(smem + OFF_PS);
    #pragma unroll
    for (int i = 0; i < 2; i++) {
        vs[tid + i * 256] = v[tid + i * 256];
        ps[tid + i * 256] = g_proj_h[(size_t)b * A_ + tid + i * 256];
    }
    __syncthreads();   // tile writes visible CTA-wide before cp.async reads

    uint32_t eDst[2]; const __half* eSrc[2];
    #pragma unroll
    for (int i = 0; i < 2; i++) {
        int idx = tid + i * 256, row = idx >> 3, seg = idx & 7;
        eDst[i] = OFF_E + (uint32_t)row * 128 + (((uint32_t)seg * 16) ^ (((uint32_t)row & 7) * 16));
        eSrc[i] = g_enc_h + (size_t)(m0 + row) * D_ + seg * 8;
    }
    uint32_t wDst[8]; const __half* wSrc[8];
    #pragma unroll
    for (int i = 0; i < 8; i++) {
        int idx = tid + i * 256, row = idx >> 3, seg = idx & 7;
        wDst[i] = OFF_W + (uint32_t)row * 128 + (((uint32_t)seg * 16) ^ (((uint32_t)row & 7) * 16));
        wSrc[i] = g_We_h + (size_t)row * D_ + seg * 8;
    }

    const uint32_t xr = (uint32_t)(lane & 7) * 16;
    const uint32_t eBase = OFF_E + (uint32_t)(wm * 32 + (lane & 15)) * 128;
    const uint32_t eT = (uint32_t)(lane >> 4) * 16;
    const int q = lane >> 3;
    const uint32_t wBase = OFF_W + (uint32_t)(wn * 64 + ((q >> 1) << 3) + (lane & 7)) * 128;
    const uint32_t wT = (uint32_t)(q & 1) * 16;

    float c[2][8][4];
    float sp[4] = {0.f, 0.f, 0.f, 0.f};
    #pragma unroll
    for (int i = 0; i < 2; i++)
        #pragma unroll
        for (int j = 0; j < 8; j++)
            #pragma unroll
            for (int e = 0; e < 4; e++) c[i][j][e] = 0.f;

    auto issue = [&](int ci) {
        const int koff = (ci & 7) * 64;
        const int woff = (ci >> 3) * 256 * D_ + koff;
        const uint32_t st = sb + (uint32_t)(ci & 1) * STG;
        #pragma unroll
        for (int i = 0; i < 2; i++)
            CP16(st + eDst[i], (const char*)(eSrc[i] + koff));
        #pragma unroll
        for (int i = 0; i < 8; i++)
            CP16(st + wDst[i], (const char*)(wSrc[i] + woff));
    };

    issue(0); CP_COMMIT();

    #pragma unroll 1
    for (int ci = 0; ci < 16; ci++) {
        if (ci + 1 < 16) { issue(ci + 1); CP_COMMIT(); CP_WAIT1(); }
        else             { CP_WAIT0(); }
        __syncthreads();

        const uint32_t stb = sb + (uint32_t)(ci & 1) * STG;
        #pragma unroll
        for (int s = 0; s < 4; s++) {
            uint32_t aF[2][4];
            #pragma unroll
            for (int i = 0; i < 2; i++)
                LDSM_X4(aF[i], stb + eBase + (uint32_t)i * 2048 + (((uint32_t)s * 32 + eT) ^ xr));
            #pragma unroll
            for (int g = 0; g < 4; g++) {
                uint32_t bF[4];
                LDSM_X4(bF, stb + wBase + (uint32_t)g * 2048 + (((uint32_t)s * 32 + wT) ^ xr));
                #pragma unroll
                for (int i = 0; i < 2; i++) {
                    MMA_F16(c[i][2*g],   aF[i], bF[0], bF[1]);
                    MMA_F16(c[i][2*g+1], aF[i], bF[2], bF[3]);
                }
            }
        }
        __syncthreads();

        if ((ci & 7) == 7) {
            const int a0 = (ci >> 3) * 256;
            #pragma unroll
            for (int i = 0; i < 2; i++)
                #pragma unroll
                for (int j = 0; j < 8; j++)
                    #pragma unroll
                    for (int e = 0; e < 4; e++) {
                        int col = a0 + wn * 64 + j * 8 + (lane & 3) * 2 + (e & 1);
                        float x  = ps[col] + c[i][j][e];
                        float th;
                        asm("tanh.approx.f32 %0, %1;" : "=f"(th) : "f"(x));
                        sp[i * 2 + (e >> 1)] += vs[col] * th;
                        c[i][j][e] = 0.f;
                    }
        }
    }

    #pragma unroll
    for (int slot = 0; slot < 4; slot++) {
        sp[slot] += __shfl_xor_sync(0xffffffffu, sp[slot], 1);
        sp[slot] += __shfl_xor_sync(0xffffffffu, sp[slot], 2);
    }
    float* red = (float*)(smem + OFF_RED);
    __syncthreads();
    if ((lane & 3) == 0) {
        #pragma unroll
        for (int slot = 0; slot < 4; slot++) {
            int row = wm * 32 + (slot >> 1) * 16 + (slot & 1) * 8 + (lane >> 2);
            red[row * 4 + wn] = sp[slot];
        }
    }
    __syncthreads();
    if (tid < 64)
        g_scores[m0 + tid] = red[tid*4+0] + red[tid*4+1] + red[tid*4+2] + red[tid*4+3];
}

// ---------------------------------------------------------------------------
// fused softmax+context: grid (B, 8), 64 d-cols per block, 512 threads.
// ---------------------------------------------------------------------------
__global__ __launch_bounds__(512)
void sc_kernel(const int* __restrict__ mask,
               float* __restrict__ alpha,
               float* __restrict__ ctx) {
    __shared__ float sal[N_];
    __shared__ float sred[512];
    __shared__ float part[512 * 8];
    const int b  = blockIdx.x;
    const int d0 = blockIdx.y * 64;
    const int t  = threadIdx.x;
    const float* sc = g_scores + (size_t)b * N_;
    const int*   mk = mask     + (size_t)b * N_;

    float vals[4];
    float mx = -3.4e38f;
    #pragma unroll
    for (int i = 0; i < 4; i++) {
        int n = t + i * 512;
        float s = (mk[n] == 0) ? NEG_INF_ : sc[n];
        vals[i] = s;
        mx = fmaxf(mx, s);
    }
    sred[t] = mx;
    __syncthreads();
    #pragma unroll
    for (int o = 256; o > 0; o >>= 1) {
        if (t < o) sred[t] = fmaxf(sred[t], sred[t + o]);
        __syncthreads();
    }
    mx = sred[0];
    __syncthreads();
    float sum = 0.f;
    #pragma unroll
    for (int i = 0; i < 4; i++) { vals[i] = expf(vals[i] - mx); sum += vals[i]; }
    sred[t] = sum;
    __syncthreads();
    #pragma unroll
    for (int o = 256; o > 0; o >>= 1) {
        if (t < o) sred[t] += sred[t + o];
        __syncthreads();
    }
    const float inv = 1.f / sred[0];
    #pragma unroll
    for (int i = 0; i < 4; i++) {
        int n = t + i * 512;
        float a = vals[i] * inv;
        sal[n] = a;
        if (blockIdx.y == 0) alpha[(size_t)b * N_ + n] = a;
    }
    __syncthreads();

    const int dg = t & 7;
    const int nl = t >> 3;
    const __half* base = g_enc_h + (size_t)b * N_ * D_ + d0 + dg * 8;

    float acc[8];
    #pragma unroll
    for (int j = 0; j < 8; j++) acc[j] = 0.f;

    #pragma unroll 1
    for (int n = nl; n < N_; n += 512) {
        uint4 pk[8];
        float av[8];
        #pragma unroll
        for (int s = 0; s < 8; s++) {
            int nn = n + s * 64;
            av[s] = sal[nn];
            pk[s] = *(const uint4*)(base + (size_t)nn * D_);
        }
        #pragma unroll
        for (int s = 0; s < 8; s++) {
            float a = av[s];
            float2 f0 = __half22float2(*(const __half2*)&pk[s].x);
            float2 f1 = __half22float2(*(const __half2*)&pk[s].y);
            float2 f2 = __half22float2(*(const __half2*)&pk[s].z);
            float2 f3 = __half22float2(*(const __half2*)&pk[s].w);
            acc[0] += a * f0.x; acc[1] += a * f0.y;
            acc[2] += a * f1.x; acc[3] += a * f1.y;
            acc[4] += a * f2.x; acc[5] += a * f2.y;
            acc[6] += a * f3.x; acc[7] += a * f3.y;
        }
    }
    #pragma unroll
    for (int j = 0; j < 8; j++) part[t * 8 + j] = acc[j];
    __syncthreads();
    if (t < 64) {
        int g = t >> 3, j = t & 7;
        float s = 0.f;
        #pragma unroll
        for (int m = 0; m < 64; m++) s += part[(g + 8 * m) * 8 + j];
        ctx[(size_t)b * D_ + d0 + g * 8 + j] = s;
    }
}

// ---------------------------------------------------------------------------
extern "C" void kernel_launch(void* const* d_in, const int* in_sizes, int n_in,
                              void* d_out, int out_size) {
    const float* h    = (const float*)d_in[0];
    const float* enc  = (const float*)d_in[1];
    const int*   mask = (const int*)  d_in[2];
    const float* Wh   = (const float*)d_in[3];
    const float* We   = (const float*)d_in[4];
    const float* v    = (const float*)d_in[5];

    float* out   = (float*)d_out;
    float* ctx   = out;               // (B, D) first
    float* alpha = out + B_ * D_;     // (B, N) second

    cudaFuncSetAttribute(scores_kernel, cudaFuncAttributeMaxDynamicSharedMemorySize, SMEM_BYTES);

    prep_kernel   <<<NB_PREP, 256>>>(h, Wh, We);
    scores_kernel <<<M_ / 64, 256, SMEM_BYTES>>>(enc, v);
    sc_kernel     <<<dim3(B_, 8), 512>>>(mask, alpha, ctx);
}